// round 10
// baseline (speedup 1.0000x reference)
#include <cuda_runtime.h>

// Soft 5x5 dilation:  y = logsumexp((w + patch)*B)/B
// Factored:  y = log2( conv5x5( exp2(c*x), exp2(c*w) ) ) * (ln2/B),  c = B*log2e
// Zero-pad of x -> pad value 1.0 in exp-space.
// Conv: packed fma.rn.f32x2; taps fetched per-use as broadcast LDS.64 from
// pre-packed smem (frees ~50 regs -> 10 CTAs/SM instead of 8).

#define KK 5
#define BETA 15.0f
#define CC 64
#define HH 128
#define WW 128
#define BB 4

#define TILE_H 16
#define SROWS (TILE_H + 4)      // 20
#define SCOLS 132               // smem col = input col + 2
#define NT 128

#define B_LOG2E (BETA * 1.44269504f)
#define LN2_OVER_B (0.69314718f / BETA)

typedef unsigned long long u64;

__device__ __forceinline__ float fast_ex2(float v) {
    float r; asm("ex2.approx.ftz.f32 %0, %1;" : "=f"(r) : "f"(v)); return r;
}
__device__ __forceinline__ float fast_lg2(float v) {
    float r; asm("lg2.approx.ftz.f32 %0, %1;" : "=f"(r) : "f"(v)); return r;
}

union F2U { float2 f; u64 u; };
__device__ __forceinline__ float2 ffma2(float2 a, float2 b, float2 c) {
    F2U A, B, C, D; A.f = a; B.f = b; C.f = c;
    asm("fma.rn.f32x2 %0, %1, %2, %3;" : "=l"(D.u) : "l"(A.u), "l"(B.u), "l"(C.u));
    return D.f;
}

__global__ __launch_bounds__(NT, 10)
void morph_soft_dilate_kernel(const float* __restrict__ x,
                              const float* __restrict__ wy,
                              float* __restrict__ out)
{
    __shared__ float  sE[SROWS][SCOLS];   // 10560 B
    __shared__ float2 sA2[32];            // taps pre-duplicated into both f32x2 lanes

    const int img   = blockIdx.y;          // b*C + c
    const int c     = img & (CC - 1);
    const int tileY = blockIdx.x * TILE_H;
    const int t     = threadIdx.x;
    const int lane  = t & 31;
    const int r0    = t >> 5;

    const float* xi = x + (size_t)img * (HH * WW);

    // hoisted predicated LDG batch (MLP=5)
    float4 v[5];
    bool ok[5];
    #pragma unroll
    for (int p = 0; p < 5; p++) {
        int gr = tileY + r0 + 4 * p - 2;
        ok[p] = (gr >= 0) && (gr < HH);
        if (ok[p]) v[p] = *(const float4*)&xi[gr * WW + 4 * lane];
    }

    // setup overlapping LDG latency
    if (t < KK * KK) {
        float w0 = fast_ex2(B_LOG2E * wy[c * KK * KK + t]);
        sA2[t] = make_float2(w0, w0);
    }
    if (t < 40) {                       // halo cols 0,1,130,131 for all 20 rows
        int r  = t >> 1;
        int cb = (t & 1) ? 130 : 0;
        sE[r][cb]     = 1.0f;
        sE[r][cb + 1] = 1.0f;
    }
    {                                   // pad rows at true image edges only
        float4* sp = (float4*)&sE[0][0];
        const float4 ones = make_float4(1.f, 1.f, 1.f, 1.f);
        if (tileY == 0 && t < 66)              sp[t] = ones;        // rows 0,1
        if (tileY == HH - TILE_H && t < 66)    sp[594 + t] = ones;  // rows 18,19
    }

    // convert + STS
    #pragma unroll
    for (int p = 0; p < 5; p++) {
        if (ok[p]) {
            int r = r0 + 4 * p;
            float2 e01 = make_float2(fast_ex2(B_LOG2E * v[p].x), fast_ex2(B_LOG2E * v[p].y));
            float2 e23 = make_float2(fast_ex2(B_LOG2E * v[p].z), fast_ex2(B_LOG2E * v[p].w));
            *(float2*)&sE[r][4 * lane + 2] = e01;
            *(float2*)&sE[r][4 * lane + 4] = e23;
        }
    }
    __syncthreads();

    const int cg = lane;            // output cols 4*cg .. 4*cg+3
    const int sy = r0 * 4;          // output rows tileY+sy .. +3

    float2 acc01[4], acc23[4];
    #pragma unroll
    for (int q = 0; q < 4; q++) {
        acc01[q] = make_float2(0.f, 0.f);
        acc23[q] = make_float2(0.f, 0.f);
    }

    // 8 smem rows feed the 4x4 patch; per row: 2x LDS.128 window + broadcast
    // LDS.64 taps at use (keeps register count low for 10-CTA residency)
    #pragma unroll
    for (int rr = 0; rr < 8; rr++) {
        float4 q0 = *(const float4*)&sE[sy + rr][4 * cg];
        float4 q1 = *(const float4*)&sE[sy + rr][4 * cg + 4];
        float2 p[7];
        p[0] = make_float2(q0.x, q0.y);
        p[1] = make_float2(q0.y, q0.z);
        p[2] = make_float2(q0.z, q0.w);
        p[3] = make_float2(q0.w, q1.x);
        p[4] = make_float2(q1.x, q1.y);
        p[5] = make_float2(q1.y, q1.z);
        p[6] = make_float2(q1.z, q1.w);
        #pragma unroll
        for (int ky = 0; ky < KK; ky++) {
            int vo = rr - ky;
            if (vo >= 0 && vo < 4) {
                #pragma unroll
                for (int kx = 0; kx < KK; kx++) {
                    float2 a = sA2[ky * KK + kx];   // broadcast LDS.64
                    acc01[vo] = ffma2(a, p[kx],     acc01[vo]);
                    acc23[vo] = ffma2(a, p[kx + 2], acc23[vo]);
                }
            }
        }
    }

    float* oi = out + (size_t)img * (HH * WW);
    #pragma unroll
    for (int q = 0; q < 4; q++) {
        float4 o;
        o.x = fast_lg2(acc01[q].x) * LN2_OVER_B;
        o.y = fast_lg2(acc01[q].y) * LN2_OVER_B;
        o.z = fast_lg2(acc23[q].x) * LN2_OVER_B;
        o.w = fast_lg2(acc23[q].y) * LN2_OVER_B;
        *(float4*)&oi[(tileY + sy + q) * WW + 4 * cg] = o;
    }
}

extern "C" void kernel_launch(void* const* d_in, const int* in_sizes, int n_in,
                              void* d_out, int out_size)
{
    const float* x  = (const float*)d_in[0];   // (4, 64, 128, 128) fp32
    const float* wy = (const float*)d_in[1];   // (64, 5, 5) fp32
    float* out = (float*)d_out;                // (4, 64, 128, 128) fp32

    dim3 grid(HH / TILE_H, BB * CC);           // (8, 256) = 2048 blocks
    morph_soft_dilate_kernel<<<grid, NT>>>(x, wy, out);
}

// round 11
// speedup vs baseline: 1.3433x; 1.3433x over previous
#include <cuda_runtime.h>

// Soft 5x5 dilation:  y = logsumexp((w + patch)*B)/B
// Factored:  y = log2( conv5x5( exp2(c*x), exp2(c*w) ) ) * (ln2/B),  c = B*log2e
// Zero-pad of x -> pad value 1.0 in exp-space.
// Block = two stacked 16-row tiles, ONE 36-row smem buffer, ONE barrier;
// compute is two sequential R5-identical 4x4 packed-FFMA2 patches.

#define KK 5
#define BETA 15.0f
#define CC 64
#define HH 128
#define WW 128
#define BB 4

#define TILE2_H 32              // rows produced per block
#define SROWS (TILE2_H + 4)     // 36
#define SCOLS 132               // smem col = input col + 2
#define NT 128

#define B_LOG2E (BETA * 1.44269504f)
#define LN2_OVER_B (0.69314718f / BETA)

typedef unsigned long long u64;

__device__ __forceinline__ float fast_ex2(float v) {
    float r; asm("ex2.approx.ftz.f32 %0, %1;" : "=f"(r) : "f"(v)); return r;
}
__device__ __forceinline__ float fast_lg2(float v) {
    float r; asm("lg2.approx.ftz.f32 %0, %1;" : "=f"(r) : "f"(v)); return r;
}

union F2U { float2 f; u64 u; };
__device__ __forceinline__ float2 ffma2(float2 a, float2 b, float2 c) {
    F2U A, B, C, D; A.f = a; B.f = b; C.f = c;
    asm("fma.rn.f32x2 %0, %1, %2, %3;" : "=l"(D.u) : "l"(A.u), "l"(B.u), "l"(C.u));
    return D.f;
}

__global__ __launch_bounds__(NT, 8)
void morph_soft_dilate_kernel(const float* __restrict__ x,
                              const float* __restrict__ wy,
                              float* __restrict__ out)
{
    __shared__ float sE[SROWS][SCOLS];   // 19008 B
    __shared__ float sA[32];

    const int img   = blockIdx.y;           // b*C + c
    const int c     = img & (CC - 1);
    const int tileY = blockIdx.x * TILE2_H; // 0,32,64,96
    const int t     = threadIdx.x;
    const int lane  = t & 31;
    const int r0    = t >> 5;

    const float* xi = x + (size_t)img * (HH * WW);

    // hoisted predicated LDG batch: 9 rows/thread (rows r0+4i), MLP up to 9
    float4 v[9];
    bool ok[9];
    #pragma unroll
    for (int p = 0; p < 9; p++) {
        int gr = tileY + r0 + 4 * p - 2;
        ok[p] = (gr >= 0) && (gr < HH);
        if (ok[p]) v[p] = *(const float4*)&xi[gr * WW + 4 * lane];
    }

    // setup overlapping LDG latency
    if (t < KK * KK)
        sA[t] = fast_ex2(B_LOG2E * wy[c * KK * KK + t]);
    if (t < 72) {                       // halo cols 0,1,130,131 for all 36 rows
        int r  = t >> 1;
        int cb = (t & 1) ? 130 : 0;
        sE[r][cb]     = 1.0f;
        sE[r][cb + 1] = 1.0f;
    }
    {                                   // pad rows at true image edges only
        float4* sp = (float4*)&sE[0][0];
        const float4 ones = make_float4(1.f, 1.f, 1.f, 1.f);
        if (tileY == 0 && t < 66)               sp[t] = ones;         // rows 0,1
        if (tileY == HH - TILE2_H && t < 66)    sp[1122 + t] = ones;  // rows 34,35 (34*132/4)
    }

    // convert + STS
    #pragma unroll
    for (int p = 0; p < 9; p++) {
        if (ok[p]) {
            int r = r0 + 4 * p;
            float2 e01 = make_float2(fast_ex2(B_LOG2E * v[p].x), fast_ex2(B_LOG2E * v[p].y));
            float2 e23 = make_float2(fast_ex2(B_LOG2E * v[p].z), fast_ex2(B_LOG2E * v[p].w));
            *(float2*)&sE[r][4 * lane + 2] = e01;
            *(float2*)&sE[r][4 * lane + 4] = e23;
        }
    }
    __syncthreads();

    // taps duplicated into both f32x2 lanes (register-resident, R5 balance)
    float2 a2[KK * KK];
    #pragma unroll
    for (int i = 0; i < KK * KK; i++) { float w0 = sA[i]; a2[i] = make_float2(w0, w0); }

    const int cg = lane;                 // output cols 4*cg .. 4*cg+3
    float* oi = out + (size_t)img * (HH * WW);

    // two sequential 4x4 patches (rows r0*4 and 16+r0*4), R5-identical core
    #pragma unroll
    for (int half = 0; half < 2; half++) {
        const int sy = r0 * 4 + half * 16;

        float2 acc01[4], acc23[4];
        #pragma unroll
        for (int q = 0; q < 4; q++) {
            acc01[q] = make_float2(0.f, 0.f);
            acc23[q] = make_float2(0.f, 0.f);
        }

        #pragma unroll
        for (int rr = 0; rr < 8; rr++) {
            float4 q0 = *(const float4*)&sE[sy + rr][4 * cg];
            float4 q1 = *(const float4*)&sE[sy + rr][4 * cg + 4];
            float2 p[7];
            p[0] = make_float2(q0.x, q0.y);
            p[1] = make_float2(q0.y, q0.z);
            p[2] = make_float2(q0.z, q0.w);
            p[3] = make_float2(q0.w, q1.x);
            p[4] = make_float2(q1.x, q1.y);
            p[5] = make_float2(q1.y, q1.z);
            p[6] = make_float2(q1.z, q1.w);
            #pragma unroll
            for (int ky = 0; ky < KK; ky++) {
                int vo = rr - ky;
                if (vo >= 0 && vo < 4) {
                    #pragma unroll
                    for (int kx = 0; kx < KK; kx++) {
                        acc01[vo] = ffma2(a2[ky * KK + kx], p[kx],     acc01[vo]);
                        acc23[vo] = ffma2(a2[ky * KK + kx], p[kx + 2], acc23[vo]);
                    }
                }
            }
        }

        #pragma unroll
        for (int q = 0; q < 4; q++) {
            float4 o;
            o.x = fast_lg2(acc01[q].x) * LN2_OVER_B;
            o.y = fast_lg2(acc01[q].y) * LN2_OVER_B;
            o.z = fast_lg2(acc23[q].x) * LN2_OVER_B;
            o.w = fast_lg2(acc23[q].y) * LN2_OVER_B;
            *(float4*)&oi[(tileY + sy + q) * WW + 4 * cg] = o;
        }
    }
}

extern "C" void kernel_launch(void* const* d_in, const int* in_sizes, int n_in,
                              void* d_out, int out_size)
{
    const float* x  = (const float*)d_in[0];   // (4, 64, 128, 128) fp32
    const float* wy = (const float*)d_in[1];   // (64, 5, 5) fp32
    float* out = (float*)d_out;                // (4, 64, 128, 128) fp32

    dim3 grid(HH / TILE2_H, BB * CC);          // (4, 256) = 1024 blocks
    morph_soft_dilate_kernel<<<grid, NT>>>(x, wy, out);
}